// round 1
// baseline (speedup 1.0000x reference)
#include <cuda_runtime.h>
#include <cuda_bf16.h>
#include <math_constants.h>

#define SEQ 2048
#define HID 1024
#define NH  16
#define HD  64
#define QKV_N (3 * HID)

// Scratch (no dynamic allocation allowed)
__device__ float g_qkv[SEQ * QKV_N];   // [2048, 3072] q|k|v
__device__ float g_attn[SEQ * HID];    // [2048, 1024]

// ---------------------------------------------------------------------------
// Classic fp32 SGEMM with bias: C[M,N] = A[M,K] @ B[K,N] + bias[N]
// BM=BN=128, BK=8, TM=TN=8, 256 threads
// ---------------------------------------------------------------------------
__global__ __launch_bounds__(256) void sgemm_bias(
    int M, int N, int K,
    const float* __restrict__ A,
    const float* __restrict__ B,
    const float* __restrict__ bias,
    float* __restrict__ C)
{
    const int BM = 128, BN = 128, BK = 8, TM = 8, TN = 8;
    __shared__ float As[BK * BM];  // transposed: As[k][m]
    __shared__ float Bs[BK * BN];  // Bs[k][n]

    const int tid = threadIdx.x;
    const int blockRow = blockIdx.y * BM;
    const int blockCol = blockIdx.x * BN;

    const int tRow = (tid / (BN / TN)) * TM;   // 0..120 step 8
    const int tCol = (tid % (BN / TN)) * TN;   // 0..120 step 8

    // A tile loaders: 128x8 floats, one float4 per thread
    const int aRow = tid >> 1;          // 0..127
    const int aCol = (tid & 1) * 4;     // 0 or 4
    // B tile loaders: 8x128 floats, one float4 per thread
    const int bRow = tid >> 5;          // 0..7
    const int bCol = (tid & 31) * 4;    // 0..124

    float acc[TM][TN];
#pragma unroll
    for (int i = 0; i < TM; i++)
#pragma unroll
        for (int j = 0; j < TN; j++) acc[i][j] = 0.0f;

    const float* Aptr = A + (size_t)(blockRow + aRow) * K + aCol;
    const float* Bptr = B + (size_t)bRow * N + blockCol + bCol;

    for (int k0 = 0; k0 < K; k0 += BK) {
        float4 a4 = *reinterpret_cast<const float4*>(Aptr + k0);
        As[(aCol + 0) * BM + aRow] = a4.x;
        As[(aCol + 1) * BM + aRow] = a4.y;
        As[(aCol + 2) * BM + aRow] = a4.z;
        As[(aCol + 3) * BM + aRow] = a4.w;
        float4 b4 = *reinterpret_cast<const float4*>(Bptr + (size_t)k0 * N);
        *reinterpret_cast<float4*>(&Bs[bRow * BN + bCol]) = b4;
        __syncthreads();

#pragma unroll
        for (int kk = 0; kk < BK; kk++) {
            float ar[TM], br[TN];
            float4 a0 = *reinterpret_cast<const float4*>(&As[kk * BM + tRow]);
            float4 a1 = *reinterpret_cast<const float4*>(&As[kk * BM + tRow + 4]);
            ar[0]=a0.x; ar[1]=a0.y; ar[2]=a0.z; ar[3]=a0.w;
            ar[4]=a1.x; ar[5]=a1.y; ar[6]=a1.z; ar[7]=a1.w;
            float4 b0 = *reinterpret_cast<const float4*>(&Bs[kk * BN + tCol]);
            float4 b1 = *reinterpret_cast<const float4*>(&Bs[kk * BN + tCol + 4]);
            br[0]=b0.x; br[1]=b0.y; br[2]=b0.z; br[3]=b0.w;
            br[4]=b1.x; br[5]=b1.y; br[6]=b1.z; br[7]=b1.w;
#pragma unroll
            for (int i = 0; i < TM; i++)
#pragma unroll
                for (int j = 0; j < TN; j++)
                    acc[i][j] = fmaf(ar[i], br[j], acc[i][j]);
        }
        __syncthreads();
    }

#pragma unroll
    for (int i = 0; i < TM; i++) {
        int row = blockRow + tRow + i;
#pragma unroll
        for (int j = 0; j < TN; j += 4) {
            int col = blockCol + tCol + j;
            float4 bv = *reinterpret_cast<const float4*>(&bias[col]);
            float4 o;
            o.x = acc[i][j + 0] + bv.x;
            o.y = acc[i][j + 1] + bv.y;
            o.z = acc[i][j + 2] + bv.z;
            o.w = acc[i][j + 3] + bv.w;
            *reinterpret_cast<float4*>(&C[(size_t)row * N + col]) = o;
        }
    }
}

// ---------------------------------------------------------------------------
// Causal flash attention, fp32. One block = (64 queries, 1 head).
// 256 threads = 8 warps; each warp owns 8 query rows.
// Per KV tile (64 keys): scores via 4-row x 2-key register blocking with
// XOR-swizzled K smem (conflict-free LDS.128), online softmax per row,
// PV accumulation via P staged in smem.
// Dynamic smem: Qs[64*64] Ks[64*64] Vs[64*64] Ps[64*64] = 64 KB.
// ---------------------------------------------------------------------------
__global__ __launch_bounds__(256) void attn_kernel(
    const float* __restrict__ qkv,
    float* __restrict__ out)
{
    extern __shared__ float smem[];
    float* Qs = smem;              // [64][64]
    float* Ks = smem + 4096;       // [64][64] (XOR swizzled)
    float* Vs = smem + 8192;       // [64][64]
    float* Ps = smem + 12288;      // [64][64]

    const int h  = blockIdx.y;
    const int qb = blockIdx.x;
    const int tid = threadIdx.x;
    const int warp = tid >> 5;
    const int lane = tid & 31;
    const int qbase = qb * 64;
    const int qoff = h * HD;           // column offset of q within qkv row
    const float scale = 0.125f;        // 1/sqrt(64)

    // Load Q tile (plain layout; reads are broadcast)
    for (int i = tid; i < 64 * 16; i += 256) {
        int r = i >> 4;
        int c4 = (i & 15) << 2;
        float4 v = *reinterpret_cast<const float4*>(
            &qkv[(size_t)(qbase + r) * QKV_N + qoff + c4]);
        *reinterpret_cast<float4*>(&Qs[r * 64 + c4]) = v;
    }

    float m_r[8], l_r[8], oacc[8][2];
#pragma unroll
    for (int i = 0; i < 8; i++) {
        m_r[i] = -CUDART_INF_F;
        l_r[i] = 0.0f;
        oacc[i][0] = 0.0f;
        oacc[i][1] = 0.0f;
    }

    const int k0 = lane, k1 = lane + 32;
    const int sw = (lane & 7) << 2;    // K swizzle for this lane's keys

    const int ntiles = qb + 1;
    for (int t = 0; t < ntiles; t++) {
        __syncthreads();
        // Load K (swizzled) and V (plain) tiles
        for (int i = tid; i < 64 * 16; i += 256) {
            int r = i >> 4;
            int c4 = (i & 15) << 2;
            size_t base = (size_t)(t * 64 + r) * QKV_N + qoff;
            float4 kv = *reinterpret_cast<const float4*>(&qkv[base + HID + c4]);
            *reinterpret_cast<float4*>(&Ks[r * 64 + (c4 ^ ((r & 7) << 2))]) = kv;
            float4 vv = *reinterpret_cast<const float4*>(&qkv[base + 2 * HID + c4]);
            *reinterpret_cast<float4*>(&Vs[r * 64 + c4]) = vv;
        }
        __syncthreads();

        const bool masked = (t == qb);

        // ---- Scores + online softmax (two 4-row groups) ----
#pragma unroll
        for (int rg = 0; rg < 2; rg++) {
            const int rbase = warp * 8 + rg * 4;
            float s[4][2];
#pragma unroll
            for (int i = 0; i < 4; i++) { s[i][0] = 0.0f; s[i][1] = 0.0f; }
#pragma unroll
            for (int d4 = 0; d4 < 64; d4 += 4) {
                float4 kA = *reinterpret_cast<const float4*>(&Ks[k0 * 64 + (d4 ^ sw)]);
                float4 kB = *reinterpret_cast<const float4*>(&Ks[k1 * 64 + (d4 ^ sw)]);
#pragma unroll
                for (int i = 0; i < 4; i++) {
                    float4 qv = *reinterpret_cast<const float4*>(&Qs[(rbase + i) * 64 + d4]);
                    s[i][0] = fmaf(qv.x, kA.x, s[i][0]);
                    s[i][0] = fmaf(qv.y, kA.y, s[i][0]);
                    s[i][0] = fmaf(qv.z, kA.z, s[i][0]);
                    s[i][0] = fmaf(qv.w, kA.w, s[i][0]);
                    s[i][1] = fmaf(qv.x, kB.x, s[i][1]);
                    s[i][1] = fmaf(qv.y, kB.y, s[i][1]);
                    s[i][1] = fmaf(qv.z, kB.z, s[i][1]);
                    s[i][1] = fmaf(qv.w, kB.w, s[i][1]);
                }
            }
#pragma unroll
            for (int i = 0; i < 4; i++) {
                const int r = rbase + i;        // local row index (== query in-tile idx)
                const int rr = rg * 4 + i;      // 0..7 within warp state arrays
                float s0 = s[i][0] * scale;
                float s1 = s[i][1] * scale;
                if (masked) {
                    if (k0 > r) s0 = -CUDART_INF_F;
                    if (k1 > r) s1 = -CUDART_INF_F;
                }
                float mx = fmaxf(s0, s1);
#pragma unroll
                for (int off = 16; off > 0; off >>= 1)
                    mx = fmaxf(mx, __shfl_xor_sync(0xffffffffu, mx, off));
                float mnew = fmaxf(m_r[rr], mx);
                float p0 = __expf(s0 - mnew);
                float p1 = __expf(s1 - mnew);
                float ps = p0 + p1;
#pragma unroll
                for (int off = 16; off > 0; off >>= 1)
                    ps += __shfl_xor_sync(0xffffffffu, ps, off);
                float corr = __expf(m_r[rr] - mnew);
                l_r[rr] = l_r[rr] * corr + ps;
                m_r[rr] = mnew;
                oacc[rr][0] *= corr;
                oacc[rr][1] *= corr;
                Ps[r * 64 + k0] = p0;
                Ps[r * 64 + k1] = p1;
            }
        }
        __syncwarp();

        // ---- PV accumulation (two 4-row groups) ----
#pragma unroll
        for (int rg = 0; rg < 2; rg++) {
            const int rbase = warp * 8 + rg * 4;
            float a[4][2];
#pragma unroll
            for (int i = 0; i < 4; i++) { a[i][0] = 0.0f; a[i][1] = 0.0f; }
#pragma unroll 4
            for (int k4 = 0; k4 < 64; k4 += 4) {
                float pr[4][4];
#pragma unroll
                for (int i = 0; i < 4; i++) {
                    float4 pv = *reinterpret_cast<const float4*>(&Ps[(rbase + i) * 64 + k4]);
                    pr[i][0] = pv.x; pr[i][1] = pv.y; pr[i][2] = pv.z; pr[i][3] = pv.w;
                }
#pragma unroll
                for (int kk = 0; kk < 4; kk++) {
                    float v0 = Vs[(k4 + kk) * 64 + lane];
                    float v1 = Vs[(k4 + kk) * 64 + lane + 32];
#pragma unroll
                    for (int i = 0; i < 4; i++) {
                        a[i][0] = fmaf(pr[i][kk], v0, a[i][0]);
                        a[i][1] = fmaf(pr[i][kk], v1, a[i][1]);
                    }
                }
            }
#pragma unroll
            for (int i = 0; i < 4; i++) {
                oacc[rg * 4 + i][0] += a[i][0];
                oacc[rg * 4 + i][1] += a[i][1];
            }
        }
    }

    // ---- Finalize ----
#pragma unroll
    for (int rr = 0; rr < 8; rr++) {
        const int r = warp * 8 + rr;
        float inv = 1.0f / l_r[rr];
        size_t base = (size_t)(qbase + r) * HID + h * HD;
        out[base + lane]      = oacc[rr][0] * inv;
        out[base + lane + 32] = oacc[rr][1] * inv;
    }
}

// ---------------------------------------------------------------------------
extern "C" void kernel_launch(void* const* d_in, const int* in_sizes, int n_in,
                              void* d_out, int out_size)
{
    const float* H  = (const float*)d_in[0];  // [2048,1024]
    const float* Wa = (const float*)d_in[1];  // [1024,3072]
    const float* ba = (const float*)d_in[2];  // [3072]
    const float* Wp = (const float*)d_in[3];  // [1024,1024]
    const float* bp = (const float*)d_in[4];  // [1024]
    float* out = (float*)d_out;               // [2048,1024]

    float *qkv_ptr, *attn_ptr;
    cudaGetSymbolAddress((void**)&qkv_ptr, g_qkv);
    cudaGetSymbolAddress((void**)&attn_ptr, g_attn);

    cudaFuncSetAttribute(attn_kernel,
                         cudaFuncAttributeMaxDynamicSharedMemorySize, 65536);

    // 1) QKV GEMM: [2048,1024] @ [1024,3072] + bias
    dim3 g1(QKV_N / 128, SEQ / 128);
    sgemm_bias<<<g1, 256>>>(SEQ, QKV_N, HID, H, Wa, ba, qkv_ptr);

    // 2) Causal multi-head attention
    dim3 g2(SEQ / 64, NH);
    attn_kernel<<<g2, 256, 65536>>>(qkv_ptr, attn_ptr);

    // 3) Output projection: [2048,1024] @ [1024,1024] + bias
    dim3 g3(HID / 128, SEQ / 128);
    sgemm_bias<<<g3, 256>>>(SEQ, HID, HID, attn_ptr, Wp, bp, out);
}

// round 4
// speedup vs baseline: 1.4184x; 1.4184x over previous
#include <cuda_runtime.h>
#include <cuda_bf16.h>
#include <math_constants.h>
#include <cstdint>

#define SEQ 2048
#define HID 1024
#define NH  16
#define HD  64
#define QKV_N (3 * HID)

// ---------------------------------------------------------------------------
// Scratch (no dynamic allocation allowed)
// ---------------------------------------------------------------------------
__device__ float g_qkv[SEQ * QKV_N];            // [2048, 3072] q|k|v (fp32)
__device__ float g_attn[SEQ * HID];             // [2048, 1024] attn out (fp32)
__device__ __nv_bfloat16 g_Ah[SEQ * HID];       // hidden hi
__device__ __nv_bfloat16 g_Al[SEQ * HID];       // hidden lo
__device__ __nv_bfloat16 g_Wah[QKV_N * HID];    // w_attn^T hi  [3072][1024]
__device__ __nv_bfloat16 g_Wal[QKV_N * HID];    // w_attn^T lo
__device__ __nv_bfloat16 g_Wph[HID * HID];      // w_proj^T hi  [1024][1024]
__device__ __nv_bfloat16 g_Wpl[HID * HID];      // w_proj^T lo
__device__ __nv_bfloat16 g_Ch[SEQ * HID];       // attn out hi
__device__ __nv_bfloat16 g_Cl[SEQ * HID];       // attn out lo

// ---------------------------------------------------------------------------
// Helpers (baseline PTX only: sm_80-level features)
// ---------------------------------------------------------------------------
__device__ __forceinline__ uint32_t smem_u32(const void* p) {
    uint32_t a;
    asm("{ .reg .u64 t; cvta.to.shared.u64 t, %1; cvt.u32.u64 %0, t; }"
        : "=r"(a) : "l"(p));
    return a;
}
__device__ __forceinline__ void cp_async16(uint32_t dst, const void* src) {
    asm volatile("cp.async.cg.shared.global [%0], [%1], 16;"
                 :: "r"(dst), "l"(src));
}
#define CP_COMMIT() asm volatile("cp.async.commit_group;" ::: "memory")
#define CP_WAIT(n)  asm volatile("cp.async.wait_group %0;" :: "n"(n) : "memory")

__device__ __forceinline__ void ldm_x4(uint32_t* r, uint32_t addr) {
    asm volatile("ldmatrix.sync.aligned.m8n8.x4.shared.b16 {%0,%1,%2,%3}, [%4];"
                 : "=r"(r[0]), "=r"(r[1]), "=r"(r[2]), "=r"(r[3]) : "r"(addr));
}
__device__ __forceinline__ void mma_bf16(float* d, const uint32_t* a,
                                         const uint32_t* b) {
    asm volatile(
        "mma.sync.aligned.m16n8k16.row.col.f32.bf16.bf16.f32 "
        "{%0,%1,%2,%3}, {%4,%5,%6,%7}, {%8,%9}, {%0,%1,%2,%3};"
        : "+f"(d[0]), "+f"(d[1]), "+f"(d[2]), "+f"(d[3])
        : "r"(a[0]), "r"(a[1]), "r"(a[2]), "r"(a[3]), "r"(b[0]), "r"(b[1]));
}

// ---------------------------------------------------------------------------
// Conversion kernels: fp32 -> (hi, lo) bf16
// ---------------------------------------------------------------------------
__global__ void cvt_hilo(const float* __restrict__ x,
                         __nv_bfloat16* __restrict__ hi,
                         __nv_bfloat16* __restrict__ lo, int n4) {
    int i = blockIdx.x * blockDim.x + threadIdx.x;
    if (i >= n4) return;
    float4 v = reinterpret_cast<const float4*>(x)[i];
    __nv_bfloat16 h0 = __float2bfloat16(v.x);
    __nv_bfloat16 h1 = __float2bfloat16(v.y);
    __nv_bfloat16 h2 = __float2bfloat16(v.z);
    __nv_bfloat16 h3 = __float2bfloat16(v.w);
    __nv_bfloat16 l0 = __float2bfloat16(v.x - __bfloat162float(h0));
    __nv_bfloat16 l1 = __float2bfloat16(v.y - __bfloat162float(h1));
    __nv_bfloat16 l2 = __float2bfloat16(v.z - __bfloat162float(h2));
    __nv_bfloat16 l3 = __float2bfloat16(v.w - __bfloat162float(h3));
    __nv_bfloat162 hp0 = {h0, h1}, hp1 = {h2, h3};
    __nv_bfloat162 lp0 = {l0, l1}, lp1 = {l2, l3};
    uint2 hw, lw;
    hw.x = *reinterpret_cast<uint32_t*>(&hp0);
    hw.y = *reinterpret_cast<uint32_t*>(&hp1);
    lw.x = *reinterpret_cast<uint32_t*>(&lp0);
    lw.y = *reinterpret_cast<uint32_t*>(&lp1);
    reinterpret_cast<uint2*>(hi)[i] = hw;
    reinterpret_cast<uint2*>(lo)[i] = lw;
}

// w[K][N] fp32 -> out[N][K] hi/lo bf16 (transpose + split)
__global__ void cvt_transpose(const float* __restrict__ w,
                              __nv_bfloat16* __restrict__ th,
                              __nv_bfloat16* __restrict__ tl,
                              int K, int N) {
    __shared__ float tile[32][33];
    int n0 = blockIdx.x * 32, k0 = blockIdx.y * 32;
    int tx = threadIdx.x, ty = threadIdx.y;  // 32 x 8
#pragma unroll
    for (int j = 0; j < 4; j++)
        tile[ty + 8 * j][tx] = w[(size_t)(k0 + ty + 8 * j) * N + n0 + tx];
    __syncthreads();
#pragma unroll
    for (int j = 0; j < 4; j++) {
        float v = tile[tx][ty + 8 * j];
        __nv_bfloat16 h = __float2bfloat16(v);
        __nv_bfloat16 l = __float2bfloat16(v - __bfloat162float(h));
        size_t o = (size_t)(n0 + ty + 8 * j) * K + k0 + tx;
        th[o] = h;
        tl[o] = l;
    }
}

// ---------------------------------------------------------------------------
// bf16x3 GEMM via mma.sync: C[M,N] = A[M,K] @ Bt[N,K]^T + bias (fp32 accum)
// Tile 128x128, BK=32, 256 threads (8 warps: 4m x 2n, warp tile 32x64).
// Smem rows use 80B pitch (64B data + 16B pad) -> conflict-free ldmatrix.
// ---------------------------------------------------------------------------
#define PITCH 80
#define MAT_BYTES (128 * PITCH)      // 10240
#define STAGE_BYTES (4 * MAT_BYTES)  // 40960

__global__ __launch_bounds__(256, 1) void gemm_mma_bf16x3(
    int M, int N, int K,
    const __nv_bfloat16* __restrict__ Ah, const __nv_bfloat16* __restrict__ Al,
    const __nv_bfloat16* __restrict__ Bh, const __nv_bfloat16* __restrict__ Bl,
    const float* __restrict__ bias, float* __restrict__ C)
{
    extern __shared__ char sm[];
    const uint32_t sbase = smem_u32(sm);
    const int tid = threadIdx.x;
    const int lane = tid & 31;
    const int warp = tid >> 5;
    const int wm = warp & 3;       // 0..3
    const int wn = warp >> 2;      // 0..1
    const int m0 = blockIdx.y * 128;
    const int n0 = blockIdx.x * 128;

    const __nv_bfloat16* srcs[4] = {
        Ah + (size_t)m0 * K, Al + (size_t)m0 * K,
        Bh + (size_t)n0 * K, Bl + (size_t)n0 * K };

    float acc[2][8][4];
#pragma unroll
    for (int i = 0; i < 2; i++)
#pragma unroll
        for (int j = 0; j < 8; j++)
#pragma unroll
            for (int q = 0; q < 4; q++) acc[i][j][q] = 0.0f;

    auto load_stage = [&](int s, int kc) {
#pragma unroll
        for (int i = 0; i < 8; i++) {
            int t = tid + i * 256;
            int mat = t >> 9;            // 0..3
            int r = (t >> 2) & 127;      // row within tile
            int ch = t & 3;              // 16B chunk (8 bf16)
            cp_async16(sbase + s * STAGE_BYTES + mat * MAT_BYTES + r * PITCH + ch * 16,
                       srcs[mat] + (size_t)r * K + kc * 32 + ch * 8);
        }
        CP_COMMIT();
    };

    const int NC = K / 32;
    load_stage(0, 0);

    const int g = lane >> 3;       // ldmatrix lane group 0..3
    const int rl = lane & 7;

    for (int c = 0; c < NC; c++) {
        if (c + 1 < NC) {
            load_stage((c + 1) & 1, c + 1);
            CP_WAIT(1);
        } else {
            CP_WAIT(0);
        }
        __syncthreads();

        const uint32_t st = sbase + (c & 1) * STAGE_BYTES;

#pragma unroll
        for (int k16 = 0; k16 < 2; k16++) {
            const int ch = k16 * 2 + (g >> 1);   // per-lane k-chunk for ldmatrix
            const int roff = rl + ((g & 1) << 3);

            uint32_t ah[2][4], al_[2][4];
#pragma unroll
            for (int mf = 0; mf < 2; mf++) {
                int row = wm * 32 + mf * 16 + roff;
                ldm_x4(ah[mf],  st + 0 * MAT_BYTES + row * PITCH + ch * 16);
                ldm_x4(al_[mf], st + 1 * MAT_BYTES + row * PITCH + ch * 16);
            }

            uint32_t bh_[8][2], bl_[8][2];
#pragma unroll
            for (int ng = 0; ng < 4; ng++) {
                int row = wn * 64 + ng * 16 + roff;
                uint32_t r4[4], r5[4];
                ldm_x4(r4, st + 2 * MAT_BYTES + row * PITCH + ch * 16);
                ldm_x4(r5, st + 3 * MAT_BYTES + row * PITCH + ch * 16);
                bh_[2 * ng][0] = r4[0];     bh_[2 * ng][1] = r4[2];
                bh_[2 * ng + 1][0] = r4[1]; bh_[2 * ng + 1][1] = r4[3];
                bl_[2 * ng][0] = r5[0];     bl_[2 * ng][1] = r5[2];
                bl_[2 * ng + 1][0] = r5[1]; bl_[2 * ng + 1][1] = r5[3];
            }

#pragma unroll
            for (int mf = 0; mf < 2; mf++)
#pragma unroll
                for (int nf = 0; nf < 8; nf++) {
                    mma_bf16(acc[mf][nf], ah[mf],  bh_[nf]);
                    mma_bf16(acc[mf][nf], ah[mf],  bl_[nf]);
                    mma_bf16(acc[mf][nf], al_[mf], bh_[nf]);
                }
        }
        __syncthreads();
    }

    // Epilogue: direct stores + bias
#pragma unroll
    for (int mf = 0; mf < 2; mf++) {
        int rbase = m0 + wm * 32 + mf * 16 + (lane >> 2);
#pragma unroll
        for (int nf = 0; nf < 8; nf++) {
            int col = n0 + wn * 64 + nf * 8 + (lane & 3) * 2;
            float2 bv = *reinterpret_cast<const float2*>(&bias[col]);
            float2 o0 = { acc[mf][nf][0] + bv.x, acc[mf][nf][1] + bv.y };
            float2 o1 = { acc[mf][nf][2] + bv.x, acc[mf][nf][3] + bv.y };
            *reinterpret_cast<float2*>(&C[(size_t)rbase * N + col]) = o0;
            *reinterpret_cast<float2*>(&C[(size_t)(rbase + 8) * N + col]) = o1;
        }
    }
}

// ---------------------------------------------------------------------------
// Causal flash attention, fp32 (unchanged, known-good)
// ---------------------------------------------------------------------------
__global__ __launch_bounds__(256) void attn_kernel(
    const float* __restrict__ qkv,
    float* __restrict__ out)
{
    extern __shared__ float smem[];
    float* Qs = smem;
    float* Ks = smem + 4096;
    float* Vs = smem + 8192;
    float* Ps = smem + 12288;

    const int h  = blockIdx.y;
    const int qb = blockIdx.x;
    const int tid = threadIdx.x;
    const int warp = tid >> 5;
    const int lane = tid & 31;
    const int qbase = qb * 64;
    const int qoff = h * HD;
    const float scale = 0.125f;

    for (int i = tid; i < 64 * 16; i += 256) {
        int r = i >> 4;
        int c4 = (i & 15) << 2;
        float4 v = *reinterpret_cast<const float4*>(
            &qkv[(size_t)(qbase + r) * QKV_N + qoff + c4]);
        *reinterpret_cast<float4*>(&Qs[r * 64 + c4]) = v;
    }

    float m_r[8], l_r[8], oacc[8][2];
#pragma unroll
    for (int i = 0; i < 8; i++) {
        m_r[i] = -CUDART_INF_F;
        l_r[i] = 0.0f;
        oacc[i][0] = 0.0f;
        oacc[i][1] = 0.0f;
    }

    const int k0 = lane, k1 = lane + 32;
    const int sw = (lane & 7) << 2;

    const int ntiles = qb + 1;
    for (int t = 0; t < ntiles; t++) {
        __syncthreads();
        for (int i = tid; i < 64 * 16; i += 256) {
            int r = i >> 4;
            int c4 = (i & 15) << 2;
            size_t base = (size_t)(t * 64 + r) * QKV_N + qoff;
            float4 kv = *reinterpret_cast<const float4*>(&qkv[base + HID + c4]);
            *reinterpret_cast<float4*>(&Ks[r * 64 + (c4 ^ ((r & 7) << 2))]) = kv;
            float4 vv = *reinterpret_cast<const float4*>(&qkv[base + 2 * HID + c4]);
            *reinterpret_cast<float4*>(&Vs[r * 64 + c4]) = vv;
        }
        __syncthreads();

        const bool masked = (t == qb);

#pragma unroll
        for (int rg = 0; rg < 2; rg++) {
            const int rbase = warp * 8 + rg * 4;
            float s[4][2];
#pragma unroll
            for (int i = 0; i < 4; i++) { s[i][0] = 0.0f; s[i][1] = 0.0f; }
#pragma unroll
            for (int d4 = 0; d4 < 64; d4 += 4) {
                float4 kA = *reinterpret_cast<const float4*>(&Ks[k0 * 64 + (d4 ^ sw)]);
                float4 kB = *reinterpret_cast<const float4*>(&Ks[k1 * 64 + (d4 ^ sw)]);
#pragma unroll
                for (int i = 0; i < 4; i++) {
                    float4 qv = *reinterpret_cast<const float4*>(&Qs[(rbase + i) * 64 + d4]);
                    s[i][0] = fmaf(qv.x, kA.x, s[i][0]);
                    s[i][0] = fmaf(qv.y, kA.y, s[i][0]);
                    s[i][0] = fmaf(qv.z, kA.z, s[i][0]);
                    s[i][0] = fmaf(qv.w, kA.w, s[i][0]);
                    s[i][1] = fmaf(qv.x, kB.x, s[i][1]);
                    s[i][1] = fmaf(qv.y, kB.y, s[i][1]);
                    s[i][1] = fmaf(qv.z, kB.z, s[i][1]);
                    s[i][1] = fmaf(qv.w, kB.w, s[i][1]);
                }
            }
#pragma unroll
            for (int i = 0; i < 4; i++) {
                const int r = rbase + i;
                const int rr = rg * 4 + i;
                float s0 = s[i][0] * scale;
                float s1 = s[i][1] * scale;
                if (masked) {
                    if (k0 > r) s0 = -CUDART_INF_F;
                    if (k1 > r) s1 = -CUDART_INF_F;
                }
                float mx = fmaxf(s0, s1);
#pragma unroll
                for (int off = 16; off > 0; off >>= 1)
                    mx = fmaxf(mx, __shfl_xor_sync(0xffffffffu, mx, off));
                float mnew = fmaxf(m_r[rr], mx);
                float p0 = __expf(s0 - mnew);
                float p1 = __expf(s1 - mnew);
                float ps = p0 + p1;
#pragma unroll
                for (int off = 16; off > 0; off >>= 1)
                    ps += __shfl_xor_sync(0xffffffffu, ps, off);
                float corr = __expf(m_r[rr] - mnew);
                l_r[rr] = l_r[rr] * corr + ps;
                m_r[rr] = mnew;
                oacc[rr][0] *= corr;
                oacc[rr][1] *= corr;
                Ps[r * 64 + k0] = p0;
                Ps[r * 64 + k1] = p1;
            }
        }
        __syncwarp();

#pragma unroll
        for (int rg = 0; rg < 2; rg++) {
            const int rbase = warp * 8 + rg * 4;
            float a[4][2];
#pragma unroll
            for (int i = 0; i < 4; i++) { a[i][0] = 0.0f; a[i][1] = 0.0f; }
#pragma unroll 4
            for (int k4 = 0; k4 < 64; k4 += 4) {
                float pr[4][4];
#pragma unroll
                for (int i = 0; i < 4; i++) {
                    float4 pv = *reinterpret_cast<const float4*>(&Ps[(rbase + i) * 64 + k4]);
                    pr[i][0] = pv.x; pr[i][1] = pv.y; pr[i][2] = pv.z; pr[i][3] = pv.w;
                }
#pragma unroll
                for (int kk = 0; kk < 4; kk++) {
                    float v0 = Vs[(k4 + kk) * 64 + lane];
                    float v1 = Vs[(k4 + kk) * 64 + lane + 32];
#pragma unroll
                    for (int i = 0; i < 4; i++) {
                        a[i][0] = fmaf(pr[i][kk], v0, a[i][0]);
                        a[i][1] = fmaf(pr[i][kk], v1, a[i][1]);
                    }
                }
            }
#pragma unroll
            for (int i = 0; i < 4; i++) {
                oacc[rg * 4 + i][0] += a[i][0];
                oacc[rg * 4 + i][1] += a[i][1];
            }
        }
    }

#pragma unroll
    for (int rr = 0; rr < 8; rr++) {
        const int r = warp * 8 + rr;
        float inv = 1.0f / l_r[rr];
        size_t base = (size_t)(qbase + r) * HID + h * HD;
        out[base + lane]      = oacc[rr][0] * inv;
        out[base + lane + 32] = oacc[rr][1] * inv;
    }
}

// ---------------------------------------------------------------------------
extern "C" void kernel_launch(void* const* d_in, const int* in_sizes, int n_in,
                              void* d_out, int out_size)
{
    const float* H  = (const float*)d_in[0];  // [2048,1024]
    const float* Wa = (const float*)d_in[1];  // [1024,3072]
    const float* ba = (const float*)d_in[2];  // [3072]
    const float* Wp = (const float*)d_in[3];  // [1024,1024]
    const float* bp = (const float*)d_in[4];  // [1024]
    float* out = (float*)d_out;               // [2048,1024]

    float *qkv_ptr, *attn_ptr;
    cudaGetSymbolAddress((void**)&qkv_ptr, g_qkv);
    cudaGetSymbolAddress((void**)&attn_ptr, g_attn);
    __nv_bfloat16 *Ah, *Al, *Wah, *Wal, *Wph, *Wpl, *Ch, *Cl;
    cudaGetSymbolAddress((void**)&Ah, g_Ah);
    cudaGetSymbolAddress((void**)&Al, g_Al);
    cudaGetSymbolAddress((void**)&Wah, g_Wah);
    cudaGetSymbolAddress((void**)&Wal, g_Wal);
    cudaGetSymbolAddress((void**)&Wph, g_Wph);
    cudaGetSymbolAddress((void**)&Wpl, g_Wpl);
    cudaGetSymbolAddress((void**)&Ch, g_Ch);
    cudaGetSymbolAddress((void**)&Cl, g_Cl);

    cudaFuncSetAttribute(attn_kernel,
                         cudaFuncAttributeMaxDynamicSharedMemorySize, 65536);
    cudaFuncSetAttribute(gemm_mma_bf16x3,
                         cudaFuncAttributeMaxDynamicSharedMemorySize, 2 * STAGE_BYTES);

    // 0) hi/lo conversions
    {
        int n4 = SEQ * HID / 4;
        cvt_hilo<<<(n4 + 255) / 256, 256>>>(H, Ah, Al, n4);
        dim3 gt1(QKV_N / 32, HID / 32), bt(32, 8);
        cvt_transpose<<<gt1, bt>>>(Wa, Wah, Wal, HID, QKV_N);
        dim3 gt2(HID / 32, HID / 32);
        cvt_transpose<<<gt2, bt>>>(Wp, Wph, Wpl, HID, HID);
    }

    // 1) QKV GEMM (tensor): [2048,1024] @ [1024,3072] + bias
    {
        dim3 g(QKV_N / 128, SEQ / 128);
        gemm_mma_bf16x3<<<g, 256, 2 * STAGE_BYTES>>>(SEQ, QKV_N, HID,
                                                     Ah, Al, Wah, Wal, ba, qkv_ptr);
    }

    // 2) Causal multi-head attention (fp32)
    {
        dim3 g(SEQ / 64, NH);
        attn_kernel<<<g, 256, 65536>>>(qkv_ptr, attn_ptr);
    }

    // 3) attn out -> hi/lo, then proj GEMM (tensor)
    {
        int n4 = SEQ * HID / 4;
        cvt_hilo<<<(n4 + 255) / 256, 256>>>(attn_ptr, Ch, Cl, n4);
        dim3 g(HID / 128, SEQ / 128);
        gemm_mma_bf16x3<<<g, 256, 2 * STAGE_BYTES>>>(SEQ, HID, HID,
                                                     Ch, Cl, Wph, Wpl, bp, out);
    }
}

// round 6
// speedup vs baseline: 2.7788x; 1.9592x over previous
#include <cuda_runtime.h>
#include <cuda_bf16.h>
#include <math_constants.h>
#include <cstdint>

#define SEQ 2048
#define HID 1024
#define NH  16
#define HD  64
#define QKV_N (3 * HID)

// ---------------------------------------------------------------------------
// Scratch (no dynamic allocation allowed)
// ---------------------------------------------------------------------------
__device__ __align__(128) __nv_bfloat16 g_Ah[SEQ * HID];
__device__ __align__(128) __nv_bfloat16 g_Al[SEQ * HID];
__device__ __align__(128) __nv_bfloat16 g_Wah[QKV_N * HID];
__device__ __align__(128) __nv_bfloat16 g_Wal[QKV_N * HID];
__device__ __align__(128) __nv_bfloat16 g_Wph[HID * HID];
__device__ __align__(128) __nv_bfloat16 g_Wpl[HID * HID];
__device__ __align__(128) __nv_bfloat16 g_Ch[SEQ * HID];
__device__ __align__(128) __nv_bfloat16 g_Cl[SEQ * HID];
// per-head QKV, bf16 hi/lo, layout [NH][SEQ][64]
__device__ __align__(128) __nv_bfloat16 g_Qh[NH * SEQ * HD];
__device__ __align__(128) __nv_bfloat16 g_Ql[NH * SEQ * HD];
__device__ __align__(128) __nv_bfloat16 g_Kh[NH * SEQ * HD];
__device__ __align__(128) __nv_bfloat16 g_Kl[NH * SEQ * HD];
__device__ __align__(128) __nv_bfloat16 g_Vh[NH * SEQ * HD];
__device__ __align__(128) __nv_bfloat16 g_Vl[NH * SEQ * HD];

// ---------------------------------------------------------------------------
// Helpers (baseline PTX only)
// ---------------------------------------------------------------------------
__device__ __forceinline__ uint32_t smem_u32(const void* p) {
    uint32_t a;
    asm("{ .reg .u64 t; cvta.to.shared.u64 t, %1; cvt.u32.u64 %0, t; }"
        : "=r"(a) : "l"(p));
    return a;
}
__device__ __forceinline__ void cp_async16(uint32_t dst, const void* src) {
    asm volatile("cp.async.cg.shared.global [%0], [%1], 16;"
                 :: "r"(dst), "l"(src));
}
#define CP_COMMIT() asm volatile("cp.async.commit_group;" ::: "memory")
#define CP_WAIT(n)  asm volatile("cp.async.wait_group %0;" :: "n"(n) : "memory")

__device__ __forceinline__ void ldm_x4(uint32_t* r, uint32_t addr) {
    asm volatile("ldmatrix.sync.aligned.m8n8.x4.shared.b16 {%0,%1,%2,%3}, [%4];"
                 : "=r"(r[0]), "=r"(r[1]), "=r"(r[2]), "=r"(r[3]) : "r"(addr));
}
__device__ __forceinline__ void ldm_x4_t(uint32_t* r, uint32_t addr) {
    asm volatile("ldmatrix.sync.aligned.m8n8.x4.trans.shared.b16 {%0,%1,%2,%3}, [%4];"
                 : "=r"(r[0]), "=r"(r[1]), "=r"(r[2]), "=r"(r[3]) : "r"(addr));
}
__device__ __forceinline__ void mma_bf16(float* d, const uint32_t* a,
                                         uint32_t b0, uint32_t b1) {
    asm volatile(
        "mma.sync.aligned.m16n8k16.row.col.f32.bf16.bf16.f32 "
        "{%0,%1,%2,%3}, {%4,%5,%6,%7}, {%8,%9}, {%0,%1,%2,%3};"
        : "+f"(d[0]), "+f"(d[1]), "+f"(d[2]), "+f"(d[3])
        : "r"(a[0]), "r"(a[1]), "r"(a[2]), "r"(a[3]), "r"(b0), "r"(b1));
}
__device__ __forceinline__ uint32_t pack_bf16(float a, float b) {
    __nv_bfloat162 t;
    t.x = __float2bfloat16(a);
    t.y = __float2bfloat16(b);
    return *reinterpret_cast<uint32_t*>(&t);
}

// ---------------------------------------------------------------------------
// Conversion kernels
// ---------------------------------------------------------------------------
__global__ void cvt_hilo(const float* __restrict__ x,
                         __nv_bfloat16* __restrict__ hi,
                         __nv_bfloat16* __restrict__ lo, int n4) {
    int i = blockIdx.x * blockDim.x + threadIdx.x;
    if (i >= n4) return;
    float4 v = reinterpret_cast<const float4*>(x)[i];
    __nv_bfloat16 h0 = __float2bfloat16(v.x), h1 = __float2bfloat16(v.y);
    __nv_bfloat16 h2 = __float2bfloat16(v.z), h3 = __float2bfloat16(v.w);
    uint2 hw, lw;
    hw.x = pack_bf16(v.x, v.y);
    hw.y = pack_bf16(v.z, v.w);
    lw.x = pack_bf16(v.x - __bfloat162float(h0), v.y - __bfloat162float(h1));
    lw.y = pack_bf16(v.z - __bfloat162float(h2), v.w - __bfloat162float(h3));
    reinterpret_cast<uint2*>(hi)[i] = hw;
    reinterpret_cast<uint2*>(lo)[i] = lw;
}

__global__ void cvt_transpose(const float* __restrict__ w,
                              __nv_bfloat16* __restrict__ th,
                              __nv_bfloat16* __restrict__ tl,
                              int K, int N) {
    __shared__ float tile[32][33];
    int n0 = blockIdx.x * 32, k0 = blockIdx.y * 32;
    int tx = threadIdx.x, ty = threadIdx.y;
#pragma unroll
    for (int j = 0; j < 4; j++)
        tile[ty + 8 * j][tx] = w[(size_t)(k0 + ty + 8 * j) * N + n0 + tx];
    __syncthreads();
#pragma unroll
    for (int j = 0; j < 4; j++) {
        float v = tile[tx][ty + 8 * j];
        __nv_bfloat16 h = __float2bfloat16(v);
        __nv_bfloat16 l = __float2bfloat16(v - __bfloat162float(h));
        size_t o = (size_t)(n0 + ty + 8 * j) * K + k0 + tx;
        th[o] = h;
        tl[o] = l;
    }
}

// ---------------------------------------------------------------------------
// bf16x3 GEMM via mma.sync. mode 0: fp32 C + bias. mode 1: QKV split hi/lo.
// ---------------------------------------------------------------------------
#define PITCH 80
#define MAT_BYTES (128 * PITCH)
#define STAGE_BYTES (4 * MAT_BYTES)

__global__ __launch_bounds__(256, 1) void gemm_mma_bf16x3(
    int M, int N, int K, int mode,
    const __nv_bfloat16* __restrict__ Ah, const __nv_bfloat16* __restrict__ Al,
    const __nv_bfloat16* __restrict__ Bh, const __nv_bfloat16* __restrict__ Bl,
    const float* __restrict__ bias, float* __restrict__ C,
    __nv_bfloat16* __restrict__ qh, __nv_bfloat16* __restrict__ ql,
    __nv_bfloat16* __restrict__ kh, __nv_bfloat16* __restrict__ kl,
    __nv_bfloat16* __restrict__ vh, __nv_bfloat16* __restrict__ vl)
{
    extern __shared__ char sm[];
    const uint32_t sbase = smem_u32(sm);
    const int tid = threadIdx.x;
    const int lane = tid & 31;
    const int warp = tid >> 5;
    const int wm = warp & 3;
    const int wn = warp >> 2;
    const int m0 = blockIdx.y * 128;
    const int n0 = blockIdx.x * 128;

    const __nv_bfloat16* srcs[4] = {
        Ah + (size_t)m0 * K, Al + (size_t)m0 * K,
        Bh + (size_t)n0 * K, Bl + (size_t)n0 * K };

    float acc[2][8][4];
#pragma unroll
    for (int i = 0; i < 2; i++)
#pragma unroll
        for (int j = 0; j < 8; j++)
#pragma unroll
            for (int q = 0; q < 4; q++) acc[i][j][q] = 0.0f;

    auto load_stage = [&](int s, int kc) {
#pragma unroll
        for (int i = 0; i < 8; i++) {
            int t = tid + i * 256;
            int mat = t >> 9;
            int r = (t >> 2) & 127;
            int ch = t & 3;
            cp_async16(sbase + s * STAGE_BYTES + mat * MAT_BYTES + r * PITCH + ch * 16,
                       srcs[mat] + (size_t)r * K + kc * 32 + ch * 8);
        }
        CP_COMMIT();
    };

    const int NC = K / 32;
    load_stage(0, 0);

    const int g = lane >> 3;
    const int rl = lane & 7;

    for (int c = 0; c < NC; c++) {
        if (c + 1 < NC) {
            load_stage((c + 1) & 1, c + 1);
            CP_WAIT(1);
        } else {
            CP_WAIT(0);
        }
        __syncthreads();

        const uint32_t st = sbase + (c & 1) * STAGE_BYTES;

#pragma unroll
        for (int k16 = 0; k16 < 2; k16++) {
            const int ch = k16 * 2 + (g >> 1);
            const int roff = rl + ((g & 1) << 3);

            uint32_t ah[2][4], al_[2][4];
#pragma unroll
            for (int mf = 0; mf < 2; mf++) {
                int row = wm * 32 + mf * 16 + roff;
                ldm_x4(ah[mf],  st + 0 * MAT_BYTES + row * PITCH + ch * 16);
                ldm_x4(al_[mf], st + 1 * MAT_BYTES + row * PITCH + ch * 16);
            }

            uint32_t bh_[8][2], bl_[8][2];
#pragma unroll
            for (int ng = 0; ng < 4; ng++) {
                int row = wn * 64 + ng * 16 + roff;
                uint32_t r4[4], r5[4];
                ldm_x4(r4, st + 2 * MAT_BYTES + row * PITCH + ch * 16);
                ldm_x4(r5, st + 3 * MAT_BYTES + row * PITCH + ch * 16);
                bh_[2 * ng][0] = r4[0];     bh_[2 * ng][1] = r4[2];
                bh_[2 * ng + 1][0] = r4[1]; bh_[2 * ng + 1][1] = r4[3];
                bl_[2 * ng][0] = r5[0];     bl_[2 * ng][1] = r5[2];
                bl_[2 * ng + 1][0] = r5[1]; bl_[2 * ng + 1][1] = r5[3];
            }

#pragma unroll
            for (int mf = 0; mf < 2; mf++)
#pragma unroll
                for (int nf = 0; nf < 8; nf++) {
                    mma_bf16(acc[mf][nf], ah[mf],  bh_[nf][0], bh_[nf][1]);
                    mma_bf16(acc[mf][nf], ah[mf],  bl_[nf][0], bl_[nf][1]);
                    mma_bf16(acc[mf][nf], al_[mf], bh_[nf][0], bh_[nf][1]);
                }
        }
        __syncthreads();
    }

    // Epilogue
#pragma unroll
    for (int mf = 0; mf < 2; mf++) {
        int rbase = m0 + wm * 32 + mf * 16 + (lane >> 2);
#pragma unroll
        for (int nf = 0; nf < 8; nf++) {
            int col = n0 + wn * 64 + nf * 8 + (lane & 3) * 2;
            float2 bv = *reinterpret_cast<const float2*>(&bias[col]);
            float a0 = acc[mf][nf][0] + bv.x, a1 = acc[mf][nf][1] + bv.y;
            float a2 = acc[mf][nf][2] + bv.x, a3 = acc[mf][nf][3] + bv.y;
            if (mode == 0) {
                float2 o0 = {a0, a1}, o1 = {a2, a3};
                *reinterpret_cast<float2*>(&C[(size_t)rbase * N + col]) = o0;
                *reinterpret_cast<float2*>(&C[(size_t)(rbase + 8) * N + col]) = o1;
            } else {
                int sec = col >> 10;
                int head = (col & 1023) >> 6;
                int dim = col & 63;
                __nv_bfloat16* dh = (sec == 0) ? qh : (sec == 1) ? kh : vh;
                __nv_bfloat16* dl = (sec == 0) ? ql : (sec == 1) ? kl : vl;
                size_t o0 = ((size_t)head * SEQ + rbase) * HD + dim;
                size_t o1 = o0 + 8 * HD;
                __nv_bfloat16 h0 = __float2bfloat16(a0), h1 = __float2bfloat16(a1);
                __nv_bfloat16 h2 = __float2bfloat16(a2), h3 = __float2bfloat16(a3);
                *reinterpret_cast<uint32_t*>(&dh[o0]) = pack_bf16(a0, a1);
                *reinterpret_cast<uint32_t*>(&dl[o0]) =
                    pack_bf16(a0 - __bfloat162float(h0), a1 - __bfloat162float(h1));
                *reinterpret_cast<uint32_t*>(&dh[o1]) = pack_bf16(a2, a3);
                *reinterpret_cast<uint32_t*>(&dl[o1]) =
                    pack_bf16(a2 - __bfloat162float(h2), a3 - __bfloat162float(h3));
            }
        }
    }
}

// ---------------------------------------------------------------------------
// Tensorized causal flash attention.
// Block = (64 queries, 1 head), 128 threads (4 warps x 16 rows).
// QK^T and PV via m16n8k16 bf16 with hi/lo compensation (3 MMAs each).
// Smem: stage s (32KB): Kh|Kl|Vh|Vl 64x64 bf16 tiles, XOR-swizzled 16B chunks.
// Output: Ch/Cl hi/lo bf16 [SEQ][HID].
// ---------------------------------------------------------------------------
__global__ __launch_bounds__(128, 1) void attn_mma(
    const __nv_bfloat16* __restrict__ Qh_, const __nv_bfloat16* __restrict__ Ql_,
    const __nv_bfloat16* __restrict__ Kh_, const __nv_bfloat16* __restrict__ Kl_,
    const __nv_bfloat16* __restrict__ Vh_, const __nv_bfloat16* __restrict__ Vl_,
    __nv_bfloat16* __restrict__ Ch, __nv_bfloat16* __restrict__ Cl)
{
    extern __shared__ char sm[];
    const uint32_t sb = smem_u32(sm);
    const int h = blockIdx.y;
    const int qb = blockIdx.x;
    const int tid = threadIdx.x;
    const int lane = tid & 31;
    const int warp = tid >> 5;
    const int qbase = qb * 64;
    const size_t hb = (size_t)h * SEQ * HD;
    const float scale = 0.125f;

    const __nv_bfloat16* kv[4] = { Kh_ + hb, Kl_ + hb, Vh_ + hb, Vl_ + hb };

    // ---- Load Q tile (hi/lo) to smem, extract A-fragments ----
    for (int i = tid; i < 64 * 8; i += 128) {
        int r = i >> 3, ch = i & 7;
        uint32_t sw = (uint32_t)((ch ^ (r & 7)) * 16);
        const size_t go = hb + (size_t)(qbase + r) * HD + ch * 8;
        cp_async16(sb + r * 128 + sw, Qh_ + go);
        cp_async16(sb + 8192 + r * 128 + sw, Ql_ + go);
    }
    CP_COMMIT(); CP_WAIT(0);
    __syncthreads();

    uint32_t qh[4][4], ql[4][4];
    {
        int row = warp * 16 + (lane & 15);
#pragma unroll
        for (int ks = 0; ks < 4; ks++) {
            int ch = ks * 2 + (lane >> 4);
            uint32_t a = sb + row * 128 + ((ch ^ (row & 7)) * 16);
            ldm_x4(qh[ks], a);
            ldm_x4(ql[ks], a + 8192);
        }
    }
    __syncthreads();

    float o[8][4];
#pragma unroll
    for (int i = 0; i < 8; i++)
#pragma unroll
        for (int j = 0; j < 4; j++) o[i][j] = 0.0f;
    float m0v = -CUDART_INF_F, m1v = -CUDART_INF_F;
    float l0v = 0.0f, l1v = 0.0f;

    auto load_kv = [&](int s, int t) {
#pragma unroll
        for (int i = 0; i < 16; i++) {
            int idx = tid + i * 128;
            int mat = idx >> 9;
            int r = (idx >> 3) & 63;
            int ch = idx & 7;
            cp_async16(sb + s * 32768 + mat * 8192 + r * 128 + ((ch ^ (r & 7)) * 16),
                       kv[mat] + (size_t)(t * 64 + r) * HD + ch * 8);
        }
        CP_COMMIT();
    };

    load_kv(0, 0);

    const int ntiles = qb + 1;
    for (int t = 0; t < ntiles; t++) {
        if (t + 1 < ntiles) {
            load_kv((t + 1) & 1, t + 1);
            CP_WAIT(1);
        } else {
            CP_WAIT(0);
        }
        __syncthreads();

        const uint32_t st = sb + (t & 1) * 32768;

        // ---- S = Q K^T (hi/lo 3-MMA) ----
        float s[8][4];
#pragma unroll
        for (int i = 0; i < 8; i++)
#pragma unroll
            for (int j = 0; j < 4; j++) s[i][j] = 0.0f;

#pragma unroll
        for (int ks = 0; ks < 4; ks++) {
#pragma unroll
            for (int kg = 0; kg < 4; kg++) {
                int key = kg * 16 + (lane & 15);
                int ch = ks * 2 + (lane >> 4);
                uint32_t a = st + key * 128 + ((ch ^ (key & 7)) * 16);
                uint32_t r4[4], r5[4];
                ldm_x4(r4, a);            // Kh
                ldm_x4(r5, a + 8192);     // Kl
                mma_bf16(s[2 * kg],     qh[ks], r4[0], r4[2]);
                mma_bf16(s[2 * kg],     qh[ks], r5[0], r5[2]);
                mma_bf16(s[2 * kg],     ql[ks], r4[0], r4[2]);
                mma_bf16(s[2 * kg + 1], qh[ks], r4[1], r4[3]);
                mma_bf16(s[2 * kg + 1], qh[ks], r5[1], r5[3]);
                mma_bf16(s[2 * kg + 1], ql[ks], r4[1], r4[3]);
            }
        }

        // ---- scale + causal mask + online softmax (register layout) ----
        const bool masked = (t == qb);
        const int gr = lane >> 2;
        const int c2 = (lane & 3) * 2;
        float mx0 = -CUDART_INF_F, mx1 = -CUDART_INF_F;
#pragma unroll
        for (int nf = 0; nf < 8; nf++) {
#pragma unroll
            for (int j = 0; j < 2; j++) {
                s[nf][j]     *= scale;
                s[nf][2 + j] *= scale;
                if (masked) {
                    int col = nf * 8 + c2 + j;
                    if (col > warp * 16 + gr)     s[nf][j]     = -CUDART_INF_F;
                    if (col > warp * 16 + gr + 8) s[nf][2 + j] = -CUDART_INF_F;
                }
                mx0 = fmaxf(mx0, s[nf][j]);
                mx1 = fmaxf(mx1, s[nf][2 + j]);
            }
        }
        mx0 = fmaxf(mx0, __shfl_xor_sync(0xffffffffu, mx0, 1));
        mx0 = fmaxf(mx0, __shfl_xor_sync(0xffffffffu, mx0, 2));
        mx1 = fmaxf(mx1, __shfl_xor_sync(0xffffffffu, mx1, 1));
        mx1 = fmaxf(mx1, __shfl_xor_sync(0xffffffffu, mx1, 2));

        float mn0 = fmaxf(m0v, mx0), mn1 = fmaxf(m1v, mx1);
        float sum0 = 0.0f, sum1 = 0.0f;
#pragma unroll
        for (int nf = 0; nf < 8; nf++) {
#pragma unroll
            for (int j = 0; j < 2; j++) {
                float p0 = __expf(s[nf][j] - mn0);
                float p1 = __expf(s[nf][2 + j] - mn1);
                s[nf][j] = p0;
                s[nf][2 + j] = p1;
                sum0 += p0;
                sum1 += p1;
            }
        }
        sum0 += __shfl_xor_sync(0xffffffffu, sum0, 1);
        sum0 += __shfl_xor_sync(0xffffffffu, sum0, 2);
        sum1 += __shfl_xor_sync(0xffffffffu, sum1, 1);
        sum1 += __shfl_xor_sync(0xffffffffu, sum1, 2);

        float corr0 = __expf(m0v - mn0), corr1 = __expf(m1v - mn1);
        l0v = l0v * corr0 + sum0;
        l1v = l1v * corr1 + sum1;
        m0v = mn0; m1v = mn1;
#pragma unroll
        for (int nf = 0; nf < 8; nf++) {
            o[nf][0] *= corr0; o[nf][1] *= corr0;
            o[nf][2] *= corr1; o[nf][3] *= corr1;
        }

        // ---- O += P V (hi/lo 3-MMA), P packed from registers ----
#pragma unroll
        for (int ks = 0; ks < 4; ks++) {
            uint32_t pah[4], pal[4];
#pragma unroll
            for (int half = 0; half < 2; half++) {
                float p0 = s[2 * ks + half][0], p1 = s[2 * ks + half][1];
                float p2 = s[2 * ks + half][2], p3 = s[2 * ks + half][3];
                __nv_bfloat16 h0 = __float2bfloat16(p0), h1 = __float2bfloat16(p1);
                __nv_bfloat16 h2 = __float2bfloat16(p2), h3 = __float2bfloat16(p3);
                pah[half * 2]     = pack_bf16(p0, p1);
                pah[half * 2 + 1] = pack_bf16(p2, p3);
                pal[half * 2]     = pack_bf16(p0 - __bfloat162float(h0),
                                              p1 - __bfloat162float(h1));
                pal[half * 2 + 1] = pack_bf16(p2 - __bfloat162float(h2),
                                              p3 - __bfloat162float(h3));
            }
            // A-frag order: a0=(gr,k0..7) a1=(gr+8,k0..7) a2=(gr,k8..15) a3=(gr+8,k8..15)
            uint32_t ah_[4] = { pah[0], pah[1], pah[2], pah[3] };
            uint32_t al_[4] = { pal[0], pal[1], pal[2], pal[3] };
#pragma unroll
            for (int dg = 0; dg < 4; dg++) {
                int key = ks * 16 + (lane & 15);
                int ch = dg * 2 + (lane >> 4);
                uint32_t a = st + 16384 + key * 128 + ((ch ^ (key & 7)) * 16);
                uint32_t rh[4], rl[4];
                ldm_x4_t(rh, a);            // Vh
                ldm_x4_t(rl, a + 8192);     // Vl
                mma_bf16(o[2 * dg],     ah_, rh[0], rh[1]);
                mma_bf16(o[2 * dg],     ah_, rl[0], rl[1]);
                mma_bf16(o[2 * dg],     al_, rh[0], rh[1]);
                mma_bf16(o[2 * dg + 1], ah_, rh[2], rh[3]);
                mma_bf16(o[2 * dg + 1], ah_, rl[2], rl[3]);
                mma_bf16(o[2 * dg + 1], al_, rh[2], rh[3]);
            }
        }
        __syncthreads();
    }

    // ---- Finalize: O /= l, write hi/lo bf16 to Ch/Cl [SEQ][HID] ----
    const float inv0 = 1.0f / l0v, inv1 = 1.0f / l1v;
    const int row0 = qbase + warp * 16 + (lane >> 2);
    const int col0 = h * HD + (lane & 3) * 2;
#pragma unroll
    for (int nf = 0; nf < 8; nf++) {
        int col = col0 + nf * 8;
        float a0 = o[nf][0] * inv0, a1 = o[nf][1] * inv0;
        float a2 = o[nf][2] * inv1, a3 = o[nf][3] * inv1;
        __nv_bfloat16 h0 = __float2bfloat16(a0), h1 = __float2bfloat16(a1);
        __nv_bfloat16 h2 = __float2bfloat16(a2), h3 = __float2bfloat16(a3);
        *reinterpret_cast<uint32_t*>(&Ch[(size_t)row0 * HID + col]) = pack_bf16(a0, a1);
        *reinterpret_cast<uint32_t*>(&Cl[(size_t)row0 * HID + col]) =
            pack_bf16(a0 - __bfloat162float(h0), a1 - __bfloat162float(h1));
        *reinterpret_cast<uint32_t*>(&Ch[(size_t)(row0 + 8) * HID + col]) = pack_bf16(a2, a3);
        *reinterpret_cast<uint32_t*>(&Cl[(size_t)(row0 + 8) * HID + col]) =
            pack_bf16(a2 - __bfloat162float(h2), a3 - __bfloat162float(h3));
    }
}

// ---------------------------------------------------------------------------
extern "C" void kernel_launch(void* const* d_in, const int* in_sizes, int n_in,
                              void* d_out, int out_size)
{
    const float* H  = (const float*)d_in[0];
    const float* Wa = (const float*)d_in[1];
    const float* ba = (const float*)d_in[2];
    const float* Wp = (const float*)d_in[3];
    const float* bp = (const float*)d_in[4];
    float* out = (float*)d_out;

    __nv_bfloat16 *Ah, *Al, *Wah, *Wal, *Wph, *Wpl, *Ch, *Cl;
    __nv_bfloat16 *Qh, *Ql, *Kh, *Kl, *Vh, *Vl;
    cudaGetSymbolAddress((void**)&Ah, g_Ah);
    cudaGetSymbolAddress((void**)&Al, g_Al);
    cudaGetSymbolAddress((void**)&Wah, g_Wah);
    cudaGetSymbolAddress((void**)&Wal, g_Wal);
    cudaGetSymbolAddress((void**)&Wph, g_Wph);
    cudaGetSymbolAddress((void**)&Wpl, g_Wpl);
    cudaGetSymbolAddress((void**)&Ch, g_Ch);
    cudaGetSymbolAddress((void**)&Cl, g_Cl);
    cudaGetSymbolAddress((void**)&Qh, g_Qh);
    cudaGetSymbolAddress((void**)&Ql, g_Ql);
    cudaGetSymbolAddress((void**)&Kh, g_Kh);
    cudaGetSymbolAddress((void**)&Kl, g_Kl);
    cudaGetSymbolAddress((void**)&Vh, g_Vh);
    cudaGetSymbolAddress((void**)&Vl, g_Vl);

    cudaFuncSetAttribute(gemm_mma_bf16x3,
                         cudaFuncAttributeMaxDynamicSharedMemorySize, 2 * STAGE_BYTES);
    cudaFuncSetAttribute(attn_mma,
                         cudaFuncAttributeMaxDynamicSharedMemorySize, 65536);

    // 0) hi/lo conversions
    {
        int n4 = SEQ * HID / 4;
        cvt_hilo<<<(n4 + 255) / 256, 256>>>(H, Ah, Al, n4);
        dim3 gt1(QKV_N / 32, HID / 32), bt(32, 8);
        cvt_transpose<<<gt1, bt>>>(Wa, Wah, Wal, HID, QKV_N);
        dim3 gt2(HID / 32, HID / 32);
        cvt_transpose<<<gt2, bt>>>(Wp, Wph, Wpl, HID, HID);
    }

    // 1) QKV GEMM -> per-head hi/lo Q/K/V
    {
        dim3 g(QKV_N / 128, SEQ / 128);
        gemm_mma_bf16x3<<<g, 256, 2 * STAGE_BYTES>>>(
            SEQ, QKV_N, HID, 1, Ah, Al, Wah, Wal, ba, nullptr,
            Qh, Ql, Kh, Kl, Vh, Vl);
    }

    // 2) Tensorized causal attention -> Ch/Cl
    {
        dim3 g(SEQ / 64, NH);
        attn_mma<<<g, 128, 65536>>>(Qh, Ql, Kh, Kl, Vh, Vl, Ch, Cl);
    }

    // 3) Output projection -> out (fp32 + bias)
    {
        dim3 g(HID / 128, SEQ / 128);
        gemm_mma_bf16x3<<<g, 256, 2 * STAGE_BYTES>>>(
            SEQ, HID, HID, 0, Ch, Cl, Wph, Wpl, bp, out,
            nullptr, nullptr, nullptr, nullptr, nullptr, nullptr);
    }
}